// round 6
// baseline (speedup 1.0000x reference)
#include <cuda_runtime.h>
#include <cuda_fp16.h>
#include <cstdint>

// hashNerf on sm_103 (plain target): fp32 hash encode + MLP via mma.sync m16n8k16
// f16 HMMA, fp32 accumulate; activations chained in register fragments.
// R6: R4 structure (mt-parallel accums), launch_bounds(128,4), v0 hoisted to smem.

#define LVL   16
#define TSZ   262144
#define TMASK 0x3FFFFu
#define THREADS 128
#define N_TAB {16.f,21.f,27.f,36.f,48.f,64.f,84.f,111.f,147.f,194.f,256.f,337.f,445.f,588.f,776.f,1024.f}

#define WPAD 72          // weight row stride in halves (144B -> conflict-free ldmatrix)
#define FPAD 40          // feature row stride in halves (80B, 16B-aligned rows)
#define OFF_W1 0
#define OFF_W2 2304      // 32*72
#define OFF_W3 6912      // 2304 + 64*72
#define OFF_W4 11520     // 6912 + 64*72
#define IMG_HALVES 12032 // + 64*8

__device__ __align__(16) unsigned short g_prepW[IMG_HALVES];

// ---------- helpers ----------
__device__ __forceinline__ uint32_t smem_u32(const void* p) {
    uint32_t a;
    asm("{ .reg .u64 t; cvta.to.shared.u64 t, %1; cvt.u32.u64 %0, t; }" : "=r"(a) : "l"(p));
    return a;
}
__device__ __forceinline__ uint32_t pack_h2(float lo, float hi) {
    uint32_t r;
    asm("cvt.rn.f16x2.f32 %0, %1, %2;" : "=r"(r) : "f"(hi), "f"(lo));
    return r;
}
__device__ __forceinline__ void ldsm_x4(uint32_t& r0, uint32_t& r1, uint32_t& r2, uint32_t& r3, uint32_t addr) {
    asm volatile("ldmatrix.sync.aligned.m8n8.x4.shared.b16 {%0,%1,%2,%3}, [%4];"
                 : "=r"(r0), "=r"(r1), "=r"(r2), "=r"(r3) : "r"(addr));
}
__device__ __forceinline__ void ldsm_x4_t(uint32_t& r0, uint32_t& r1, uint32_t& r2, uint32_t& r3, uint32_t addr) {
    asm volatile("ldmatrix.sync.aligned.m8n8.x4.trans.shared.b16 {%0,%1,%2,%3}, [%4];"
                 : "=r"(r0), "=r"(r1), "=r"(r2), "=r"(r3) : "r"(addr));
}
__device__ __forceinline__ void ldsm_x2_t(uint32_t& r0, uint32_t& r1, uint32_t addr) {
    asm volatile("ldmatrix.sync.aligned.m8n8.x2.trans.shared.b16 {%0,%1}, [%2];"
                 : "=r"(r0), "=r"(r1) : "r"(addr));
}
__device__ __forceinline__ void mma16816(float* c, const uint32_t* a, uint32_t b0, uint32_t b1) {
    asm volatile("mma.sync.aligned.m16n8k16.row.col.f32.f16.f16.f32 "
                 "{%0,%1,%2,%3}, {%4,%5,%6,%7}, {%8,%9}, {%0,%1,%2,%3};"
                 : "+f"(c[0]), "+f"(c[1]), "+f"(c[2]), "+f"(c[3])
                 : "r"(a[0]), "r"(a[1]), "r"(a[2]), "r"(a[3]), "r"(b0), "r"(b1));
}
__device__ __forceinline__ float lrelu(float v) { return (v >= 0.f) ? v : 0.01f * v; }

// ---------- prep: convert weights to f16 padded image ----------
__global__ void prep_kernel(const float* __restrict__ W1, const float* __restrict__ W2,
                            const float* __restrict__ W3, const float* __restrict__ W4) {
    __half* img = (__half*)g_prepW;
    for (int i = threadIdx.x; i < IMG_HALVES; i += blockDim.x) img[i] = __float2half(0.f);
    __syncthreads();
    for (int i = threadIdx.x; i < 32 * 64; i += blockDim.x)
        img[OFF_W1 + (i >> 6) * WPAD + (i & 63)] = __float2half(W1[i]);
    for (int i = threadIdx.x; i < 64 * 64; i += blockDim.x) {
        img[OFF_W2 + (i >> 6) * WPAD + (i & 63)] = __float2half(W2[i]);
        img[OFF_W3 + (i >> 6) * WPAD + (i & 63)] = __float2half(W3[i]);
    }
    for (int i = threadIdx.x; i < 64 * 3; i += blockDim.x)
        img[OFF_W4 + (i / 3) * 8 + (i % 3)] = __float2half(W4[i]);
}

// ---------- main kernel ----------
__global__ void __launch_bounds__(THREADS, 4)
hash_nerf_mma(const float* __restrict__ X, const float* __restrict__ tab,
              const float* __restrict__ b1, const float* __restrict__ b2,
              const float* __restrict__ b3, const float* __restrict__ b4,
              float* __restrict__ out, int n) {
    __shared__ __align__(16) unsigned short sW[IMG_HALVES];      // 24064 B
    __shared__ __align__(16) unsigned short sF[4][32 * FPAD];    // 10240 B
    __shared__ float sb[3][64];
    __shared__ float sb4[8];
    __shared__ float2 sV0[16];     // hoisted corner-(0,0) table entries per level

    const int tid  = threadIdx.x;
    const int warp = tid >> 5;
    const int lane = tid & 31;

    // stage weights (pre-converted) + biases + v0 row, once per CTA
    {
        const uint4* src = (const uint4*)g_prepW;
        uint4* dst = (uint4*)sW;
        for (int i = tid; i < IMG_HALVES / 8; i += THREADS) dst[i] = src[i];
    }
    if (tid < 64) { sb[0][tid] = b1[tid]; sb[1][tid] = b2[tid]; sb[2][tid] = b3[tid]; }
    if (tid < 8) sb4[tid] = (tid < 3) ? b4[tid] : 0.f;
    if (tid < 16) sV0[tid] = __ldg((const float2*)tab + (size_t)tid * TSZ);
    __syncthreads();

    // ---- hash encode (fp32, one thread = one point) ----
    const int pbase = blockIdx.x * THREADS + warp * 32;  // warp's first point
    const int pt = pbase + lane;
    const float Ntab[16] = N_TAB;
    float feat[32];
    if (pt < n) {
        const float2 xy = __ldg((const float2*)X + pt);
        const float x = xy.x, y = xy.y;
#pragma unroll
        for (int l = 0; l < LVL; l++) {
            float xs = x * Ntab[l], ys = y * Ntab[l];
            float xf = floorf(xs), yf = floorf(ys);
            unsigned xi = (unsigned)xf, yi = (unsigned)yf;
            unsigned hy = (yi * 2654435761u) & TMASK;
            unsigned hx = xi;                 // < 2^18 already
            unsigned hxy = hx ^ hy;
            const float2* tl = (const float2*)tab + (size_t)l * TSZ;
            float2 v0 = sV0[l];
            float2 v1 = __ldg(tl + hy);
            float2 v2 = __ldg(tl + hx);
            float2 v3 = __ldg(tl + hxy);
            float fx = xs - xf, fy = ys - yf;
            float cx = 1.f - fx, cy = 1.f - fy;
            float w0 = cx * cy, w1 = cx * fy, w2 = fx * cy, w3 = fx * fy;
            feat[2 * l]     = w0 * v0.x + w1 * v1.x + w2 * v2.x + w3 * v3.x;
            feat[2 * l + 1] = w0 * v0.y + w1 * v1.y + w2 * v2.y + w3 * v3.y;
        }
    } else {
#pragma unroll
        for (int i = 0; i < 32; i++) feat[i] = 0.f;
    }

    // write features (f16) to this warp's staging rows
    {
        uint32_t* frow = (uint32_t*)(sF[warp] + lane * FPAD);
#pragma unroll
        for (int i = 0; i < 16; i++) frow[i] = pack_h2(feat[2 * i], feat[2 * i + 1]);
    }
    __syncwarp();

    const uint32_t uW = smem_u32(sW);
    const uint32_t uF = smem_u32(sF[warp]);
    const int l15 = lane & 15;
    const int lhi = (lane >> 4) << 3;       // +8 halves for upper half-warp
    const int tg2 = (lane & 3) << 1;        // accumulator column pair base
    const int g   = lane >> 2;              // accumulator row base

    // A fragments: a[mtile][ktile][4]
    uint32_t a[2][4][4];
#pragma unroll
    for (int mt = 0; mt < 2; mt++)
#pragma unroll
        for (int kt = 0; kt < 2; kt++) {
            uint32_t ad = uF + (uint32_t)(((mt * 16 + l15) * FPAD + kt * 16 + lhi) * 2);
            ldsm_x4(a[mt][kt][0], a[mt][kt][1], a[mt][kt][2], a[mt][kt][3], ad);
        }

    const uint32_t woffs[3] = {OFF_W1 * 2u, OFF_W2 * 2u, OFF_W3 * 2u};
    const int nkts[3] = {2, 4, 4};

#pragma unroll 1
    for (int layer = 0; layer < 3; layer++) {
        const uint32_t wb = uW + woffs[layer];
        const int nkt = nkts[layer];
        float c[2][8][4];
#pragma unroll
        for (int mt = 0; mt < 2; mt++)
#pragma unroll
            for (int nt = 0; nt < 8; nt++) {
                float v0 = sb[layer][8 * nt + tg2];
                float v1 = sb[layer][8 * nt + tg2 + 1];
                c[mt][nt][0] = v0; c[mt][nt][1] = v1;
                c[mt][nt][2] = v0; c[mt][nt][3] = v1;
            }
#pragma unroll
        for (int kt = 0; kt < 4; kt++) {
            if (kt >= nkt) break;
#pragma unroll
            for (int n2 = 0; n2 < 4; n2++) {
                uint32_t b0, b1, b2, b3;
                uint32_t bd = wb + (uint32_t)(((kt * 16 + l15) * WPAD + n2 * 16 + lhi) * 2);
                ldsm_x4_t(b0, b1, b2, b3, bd);
#pragma unroll
                for (int mt = 0; mt < 2; mt++) {
                    mma16816(c[mt][2 * n2],     a[mt][kt], b0, b1);
                    mma16816(c[mt][2 * n2 + 1], a[mt][kt], b2, b3);
                }
            }
        }
        // leaky-relu + repack accumulators as next-layer A fragments
#pragma unroll
        for (int mt = 0; mt < 2; mt++)
#pragma unroll
            for (int j = 0; j < 4; j++) {
                a[mt][j][0] = pack_h2(lrelu(c[mt][2 * j][0]),     lrelu(c[mt][2 * j][1]));
                a[mt][j][1] = pack_h2(lrelu(c[mt][2 * j][2]),     lrelu(c[mt][2 * j][3]));
                a[mt][j][2] = pack_h2(lrelu(c[mt][2 * j + 1][0]), lrelu(c[mt][2 * j + 1][1]));
                a[mt][j][3] = pack_h2(lrelu(c[mt][2 * j + 1][2]), lrelu(c[mt][2 * j + 1][3]));
            }
    }

    // ---- layer 4: 64 -> 3 (single n8 tile, cols 3..7 zero-padded) ----
    float c4[2][4];
#pragma unroll
    for (int mt = 0; mt < 2; mt++) {
        c4[mt][0] = sb4[tg2]; c4[mt][1] = sb4[tg2 + 1];
        c4[mt][2] = sb4[tg2]; c4[mt][3] = sb4[tg2 + 1];
    }
#pragma unroll
    for (int kt = 0; kt < 4; kt++) {
        uint32_t b0, b1;
        uint32_t bd = uW + OFF_W4 * 2u + (uint32_t)(((kt * 16 + l15) * 8) * 2);
        ldsm_x2_t(b0, b1, bd);
#pragma unroll
        for (int mt = 0; mt < 2; mt++) mma16816(c4[mt], a[mt][kt], b0, b1);
    }

    // relu + predicated stores: rows (g, g+8) per m-tile, cols (tg2, tg2+1)
#pragma unroll
    for (int mt = 0; mt < 2; mt++) {
        int p0 = pbase + mt * 16 + g;
        int p1 = p0 + 8;
        float v0 = fmaxf(c4[mt][0], 0.f), v1 = fmaxf(c4[mt][1], 0.f);
        float v2 = fmaxf(c4[mt][2], 0.f), v3 = fmaxf(c4[mt][3], 0.f);
        if (tg2 < 3) {
            if (p0 < n) out[3 * p0 + tg2] = v0;
            if (p1 < n) out[3 * p1 + tg2] = v2;
        }
        if (tg2 + 1 < 3) {
            if (p0 < n) out[3 * p0 + tg2 + 1] = v1;
            if (p1 < n) out[3 * p1 + tg2 + 1] = v3;
        }
    }
}

extern "C" void kernel_launch(void* const* d_in, const int* in_sizes, int n_in,
                              void* d_out, int out_size) {
    const float* X   = (const float*)d_in[0];
    const float* tab = (const float*)d_in[1];
    const float* W1  = (const float*)d_in[2];
    const float* b1  = (const float*)d_in[3];
    const float* W2  = (const float*)d_in[4];
    const float* b2  = (const float*)d_in[5];
    const float* W3  = (const float*)d_in[6];
    const float* b3  = (const float*)d_in[7];
    const float* W4  = (const float*)d_in[8];
    const float* b4  = (const float*)d_in[9];
    float* out = (float*)d_out;

    int n = in_sizes[0] / 2;
    prep_kernel<<<1, 256>>>(W1, W2, W3, W4);
    int blocks = (n + THREADS - 1) / THREADS;
    hash_nerf_mma<<<blocks, THREADS>>>(X, tab, b1, b2, b3, b4, out, n);
}

// round 7
// speedup vs baseline: 1.7323x; 1.7323x over previous
#include <cuda_runtime.h>
#include <cuda_fp16.h>
#include <cstdint>

// hashNerf on sm_103 (plain target), R7: SPLIT kernels.
// K1: hash encode (high occupancy, gather-bound) -> f16 features in __device__ buffer.
// K2: MLP via mma.sync m16n8k16 HMMA (register fragments, R4 structure).

#define LVL   16
#define TSZ   262144
#define TMASK 0x3FFFFu
#define N_PTS_MAX 1048576
#define N_TAB {16.f,21.f,27.f,36.f,48.f,64.f,84.f,111.f,147.f,194.f,256.f,337.f,445.f,588.f,776.f,1024.f}

#define WPAD 72          // weight row stride in halves (144B -> conflict-free ldmatrix)
#define FPAD 40          // feature row stride in halves (80B, 16B-aligned rows)
#define OFF_W1 0
#define OFF_W2 2304      // 32*72
#define OFF_W3 6912      // 2304 + 64*72
#define OFF_W4 11520     // 6912 + 64*72
#define IMG_HALVES 12032 // + 64*8

__device__ __align__(16) unsigned short g_prepW[IMG_HALVES];
__device__ uint4 g_feat[N_PTS_MAX * 4];   // 32 f16 per point = 4 uint4

// ---------- helpers ----------
__device__ __forceinline__ uint32_t smem_u32(const void* p) {
    uint32_t a;
    asm("{ .reg .u64 t; cvta.to.shared.u64 t, %1; cvt.u32.u64 %0, t; }" : "=r"(a) : "l"(p));
    return a;
}
__device__ __forceinline__ uint32_t pack_h2(float lo, float hi) {
    uint32_t r;
    asm("cvt.rn.f16x2.f32 %0, %1, %2;" : "=r"(r) : "f"(hi), "f"(lo));
    return r;
}
__device__ __forceinline__ void ldsm_x4(uint32_t& r0, uint32_t& r1, uint32_t& r2, uint32_t& r3, uint32_t addr) {
    asm volatile("ldmatrix.sync.aligned.m8n8.x4.shared.b16 {%0,%1,%2,%3}, [%4];"
                 : "=r"(r0), "=r"(r1), "=r"(r2), "=r"(r3) : "r"(addr));
}
__device__ __forceinline__ void ldsm_x4_t(uint32_t& r0, uint32_t& r1, uint32_t& r2, uint32_t& r3, uint32_t addr) {
    asm volatile("ldmatrix.sync.aligned.m8n8.x4.trans.shared.b16 {%0,%1,%2,%3}, [%4];"
                 : "=r"(r0), "=r"(r1), "=r"(r2), "=r"(r3) : "r"(addr));
}
__device__ __forceinline__ void ldsm_x2_t(uint32_t& r0, uint32_t& r1, uint32_t addr) {
    asm volatile("ldmatrix.sync.aligned.m8n8.x2.trans.shared.b16 {%0,%1}, [%2];"
                 : "=r"(r0), "=r"(r1) : "r"(addr));
}
__device__ __forceinline__ void mma16816(float* c, const uint32_t* a, uint32_t b0, uint32_t b1) {
    asm volatile("mma.sync.aligned.m16n8k16.row.col.f32.f16.f16.f32 "
                 "{%0,%1,%2,%3}, {%4,%5,%6,%7}, {%8,%9}, {%0,%1,%2,%3};"
                 : "+f"(c[0]), "+f"(c[1]), "+f"(c[2]), "+f"(c[3])
                 : "r"(a[0]), "r"(a[1]), "r"(a[2]), "r"(a[3]), "r"(b0), "r"(b1));
}
__device__ __forceinline__ float lrelu(float v) { return (v >= 0.f) ? v : 0.01f * v; }

// ---------- prep: convert weights to f16 padded image ----------
__global__ void prep_kernel(const float* __restrict__ W1, const float* __restrict__ W2,
                            const float* __restrict__ W3, const float* __restrict__ W4) {
    __half* img = (__half*)g_prepW;
    for (int i = threadIdx.x; i < IMG_HALVES; i += blockDim.x) img[i] = __float2half(0.f);
    __syncthreads();
    for (int i = threadIdx.x; i < 32 * 64; i += blockDim.x)
        img[OFF_W1 + (i >> 6) * WPAD + (i & 63)] = __float2half(W1[i]);
    for (int i = threadIdx.x; i < 64 * 64; i += blockDim.x) {
        img[OFF_W2 + (i >> 6) * WPAD + (i & 63)] = __float2half(W2[i]);
        img[OFF_W3 + (i >> 6) * WPAD + (i & 63)] = __float2half(W3[i]);
    }
    for (int i = threadIdx.x; i < 64 * 3; i += blockDim.x)
        img[OFF_W4 + (i / 3) * 8 + (i % 3)] = __float2half(W4[i]);
}

// ---------- K1: hash encode ----------
__global__ void __launch_bounds__(256)
encode_kernel(const float* __restrict__ X, const float* __restrict__ tab, int n) {
    const int pt = blockIdx.x * 256 + threadIdx.x;
    if (pt >= n) return;
    const float Ntab[16] = N_TAB;
    const float2 xy = __ldg((const float2*)X + pt);
    const float x = xy.x, y = xy.y;

    uint32_t packed[16];
#pragma unroll
    for (int l = 0; l < LVL; l++) {
        float xs = x * Ntab[l], ys = y * Ntab[l];
        float xf = floorf(xs), yf = floorf(ys);
        unsigned xi = (unsigned)xf, yi = (unsigned)yf;
        unsigned hy = (yi * 2654435761u) & TMASK;
        unsigned hx = xi;                 // < 2^18 already
        unsigned hxy = hx ^ hy;
        const float2* tl = (const float2*)tab + (size_t)l * TSZ;
        float2 v0 = __ldg(tl);
        float2 v1 = __ldg(tl + hy);
        float2 v2 = __ldg(tl + hx);
        float2 v3 = __ldg(tl + hxy);
        float fx = xs - xf, fy = ys - yf;
        float cx = 1.f - fx, cy = 1.f - fy;
        float w0 = cx * cy, w1 = cx * fy, w2 = fx * cy, w3 = fx * fy;
        float f0 = w0 * v0.x + w1 * v1.x + w2 * v2.x + w3 * v3.x;
        float f1 = w0 * v0.y + w1 * v1.y + w2 * v2.y + w3 * v3.y;
        packed[l] = pack_h2(f0, f1);
    }
    uint4* dst = g_feat + (size_t)pt * 4;
#pragma unroll
    for (int i = 0; i < 4; i++)
        dst[i] = make_uint4(packed[4 * i], packed[4 * i + 1], packed[4 * i + 2], packed[4 * i + 3]);
}

// ---------- K2: MLP ----------
__global__ void __launch_bounds__(128)
mlp_kernel(const float* __restrict__ b1, const float* __restrict__ b2,
           const float* __restrict__ b3, const float* __restrict__ b4,
           float* __restrict__ out, int n) {
    __shared__ __align__(16) unsigned short sW[IMG_HALVES];      // 24064 B
    __shared__ __align__(16) unsigned short sF[4][32 * FPAD];    // 10240 B
    __shared__ float sb[3][64];
    __shared__ float sb4[8];

    const int tid  = threadIdx.x;
    const int warp = tid >> 5;
    const int lane = tid & 31;

    {
        const uint4* src = (const uint4*)g_prepW;
        uint4* dst = (uint4*)sW;
        for (int i = tid; i < IMG_HALVES / 8; i += 128) dst[i] = src[i];
    }
    if (tid < 64) { sb[0][tid] = b1[tid]; sb[1][tid] = b2[tid]; sb[2][tid] = b3[tid]; }
    if (tid < 8) sb4[tid] = (tid < 3) ? b4[tid] : 0.f;
    __syncthreads();

    const int pbase = blockIdx.x * 128 + warp * 32;  // warp's first point

    // stage this warp's 32 feature rows (coalesced uint4 copy, swizzle into FPAD rows)
    {
        const uint4* src = g_feat + (size_t)pbase * 4;   // 128 uint4
        unsigned short* dstbase = sF[warp];
#pragma unroll
        for (int i = 0; i < 4; i++) {
            int j = lane + 32 * i;                        // 0..127
            uint4 v = src[j];                             // point j>>2, slot j&3
            *(uint4*)(dstbase + (j >> 2) * FPAD + (j & 3) * 8) = v;
        }
    }
    __syncwarp();

    const uint32_t uW = smem_u32(sW);
    const uint32_t uF = smem_u32(sF[warp]);
    const int l15 = lane & 15;
    const int lhi = (lane >> 4) << 3;       // +8 halves for upper half-warp
    const int tg2 = (lane & 3) << 1;        // accumulator column pair base
    const int g   = lane >> 2;              // accumulator row base

    // A fragments: a[mtile][ktile][4]
    uint32_t a[2][4][4];
#pragma unroll
    for (int mt = 0; mt < 2; mt++)
#pragma unroll
        for (int kt = 0; kt < 2; kt++) {
            uint32_t ad = uF + (uint32_t)(((mt * 16 + l15) * FPAD + kt * 16 + lhi) * 2);
            ldsm_x4(a[mt][kt][0], a[mt][kt][1], a[mt][kt][2], a[mt][kt][3], ad);
        }

    const uint32_t woffs[3] = {OFF_W1 * 2u, OFF_W2 * 2u, OFF_W3 * 2u};
    const int nkts[3] = {2, 4, 4};

#pragma unroll 1
    for (int layer = 0; layer < 3; layer++) {
        const uint32_t wb = uW + woffs[layer];
        const int nkt = nkts[layer];
        float c[2][8][4];
#pragma unroll
        for (int mt = 0; mt < 2; mt++)
#pragma unroll
            for (int nt = 0; nt < 8; nt++) {
                float v0 = sb[layer][8 * nt + tg2];
                float v1 = sb[layer][8 * nt + tg2 + 1];
                c[mt][nt][0] = v0; c[mt][nt][1] = v1;
                c[mt][nt][2] = v0; c[mt][nt][3] = v1;
            }
#pragma unroll
        for (int kt = 0; kt < 4; kt++) {
            if (kt >= nkt) break;
#pragma unroll
            for (int n2 = 0; n2 < 4; n2++) {
                uint32_t b0, b1, b2, b3;
                uint32_t bd = wb + (uint32_t)(((kt * 16 + l15) * WPAD + n2 * 16 + lhi) * 2);
                ldsm_x4_t(b0, b1, b2, b3, bd);
#pragma unroll
                for (int mt = 0; mt < 2; mt++) {
                    mma16816(c[mt][2 * n2],     a[mt][kt], b0, b1);
                    mma16816(c[mt][2 * n2 + 1], a[mt][kt], b2, b3);
                }
            }
        }
        // leaky-relu + repack accumulators as next-layer A fragments
#pragma unroll
        for (int mt = 0; mt < 2; mt++)
#pragma unroll
            for (int j = 0; j < 4; j++) {
                a[mt][j][0] = pack_h2(lrelu(c[mt][2 * j][0]),     lrelu(c[mt][2 * j][1]));
                a[mt][j][1] = pack_h2(lrelu(c[mt][2 * j][2]),     lrelu(c[mt][2 * j][3]));
                a[mt][j][2] = pack_h2(lrelu(c[mt][2 * j + 1][0]), lrelu(c[mt][2 * j + 1][1]));
                a[mt][j][3] = pack_h2(lrelu(c[mt][2 * j + 1][2]), lrelu(c[mt][2 * j + 1][3]));
            }
    }

    // ---- layer 4: 64 -> 3 (single n8 tile, cols 3..7 zero-padded) ----
    float c4[2][4];
#pragma unroll
    for (int mt = 0; mt < 2; mt++) {
        c4[mt][0] = sb4[tg2]; c4[mt][1] = sb4[tg2 + 1];
        c4[mt][2] = sb4[tg2]; c4[mt][3] = sb4[tg2 + 1];
    }
#pragma unroll
    for (int kt = 0; kt < 4; kt++) {
        uint32_t b0, b1;
        uint32_t bd = uW + OFF_W4 * 2u + (uint32_t)(((kt * 16 + l15) * 8) * 2);
        ldsm_x2_t(b0, b1, bd);
#pragma unroll
        for (int mt = 0; mt < 2; mt++) mma16816(c4[mt], a[mt][kt], b0, b1);
    }

    // relu + predicated stores: rows (g, g+8) per m-tile, cols (tg2, tg2+1)
#pragma unroll
    for (int mt = 0; mt < 2; mt++) {
        int p0 = pbase + mt * 16 + g;
        int p1 = p0 + 8;
        float v0 = fmaxf(c4[mt][0], 0.f), v1 = fmaxf(c4[mt][1], 0.f);
        float v2 = fmaxf(c4[mt][2], 0.f), v3 = fmaxf(c4[mt][3], 0.f);
        if (tg2 < 3) {
            if (p0 < n) out[3 * p0 + tg2] = v0;
            if (p1 < n) out[3 * p1 + tg2] = v2;
        }
        if (tg2 + 1 < 3) {
            if (p0 < n) out[3 * p0 + tg2 + 1] = v1;
            if (p1 < n) out[3 * p1 + tg2 + 1] = v3;
        }
    }
}

extern "C" void kernel_launch(void* const* d_in, const int* in_sizes, int n_in,
                              void* d_out, int out_size) {
    const float* X   = (const float*)d_in[0];
    const float* tab = (const float*)d_in[1];
    const float* W1  = (const float*)d_in[2];
    const float* b1  = (const float*)d_in[3];
    const float* W2  = (const float*)d_in[4];
    const float* b2  = (const float*)d_in[5];
    const float* W3  = (const float*)d_in[6];
    const float* b3  = (const float*)d_in[7];
    const float* W4  = (const float*)d_in[8];
    const float* b4  = (const float*)d_in[9];
    float* out = (float*)d_out;

    int n = in_sizes[0] / 2;
    prep_kernel<<<1, 256>>>(W1, W2, W3, W4);
    encode_kernel<<<(n + 255) / 256, 256>>>(X, tab, n);
    mlp_kernel<<<(n + 127) / 128, 128>>>(b1, b2, b3, b4, out, n);
}

// round 8
// speedup vs baseline: 1.7934x; 1.0352x over previous
#include <cuda_runtime.h>
#include <cuda_fp16.h>
#include <cstdint>

// hashNerf on sm_103 (plain target), R8: split kernels.
// K0: parallel weight prep (1 elem/thread).
// K1: hash encode (high occupancy, gather-bound) -> f16 features in __device__ buffer.
// K2: MLP via mma.sync m16n8k16 HMMA, TILES=4 points-tiles per CTA to amortize
//     the 24KB smem weight staging (cuts 200MB L2 restage traffic to 50MB).

#define LVL   16
#define TSZ   262144
#define TMASK 0x3FFFFu
#define N_PTS_MAX 1048576
#define TILES 4
#define N_TAB {16.f,21.f,27.f,36.f,48.f,64.f,84.f,111.f,147.f,194.f,256.f,337.f,445.f,588.f,776.f,1024.f}

#define WPAD 72          // weight row stride in halves (144B -> conflict-free ldmatrix)
#define FPAD 40          // feature row stride in halves (80B, 16B-aligned rows)
#define OFF_W1 0
#define OFF_W2 2304      // 32*72
#define OFF_W3 6912      // 2304 + 64*72
#define OFF_W4 11520     // 6912 + 64*72
#define IMG_HALVES 12032 // + 64*8

__device__ __align__(16) unsigned short g_prepW[IMG_HALVES];
__device__ uint4 g_feat[N_PTS_MAX * 4];   // 32 f16 per point = 4 uint4

// ---------- helpers ----------
__device__ __forceinline__ uint32_t smem_u32(const void* p) {
    uint32_t a;
    asm("{ .reg .u64 t; cvta.to.shared.u64 t, %1; cvt.u32.u64 %0, t; }" : "=r"(a) : "l"(p));
    return a;
}
__device__ __forceinline__ uint32_t pack_h2(float lo, float hi) {
    uint32_t r;
    asm("cvt.rn.f16x2.f32 %0, %1, %2;" : "=r"(r) : "f"(hi), "f"(lo));
    return r;
}
__device__ __forceinline__ void ldsm_x4(uint32_t& r0, uint32_t& r1, uint32_t& r2, uint32_t& r3, uint32_t addr) {
    asm volatile("ldmatrix.sync.aligned.m8n8.x4.shared.b16 {%0,%1,%2,%3}, [%4];"
                 : "=r"(r0), "=r"(r1), "=r"(r2), "=r"(r3) : "r"(addr));
}
__device__ __forceinline__ void ldsm_x4_t(uint32_t& r0, uint32_t& r1, uint32_t& r2, uint32_t& r3, uint32_t addr) {
    asm volatile("ldmatrix.sync.aligned.m8n8.x4.trans.shared.b16 {%0,%1,%2,%3}, [%4];"
                 : "=r"(r0), "=r"(r1), "=r"(r2), "=r"(r3) : "r"(addr));
}
__device__ __forceinline__ void ldsm_x2_t(uint32_t& r0, uint32_t& r1, uint32_t addr) {
    asm volatile("ldmatrix.sync.aligned.m8n8.x2.trans.shared.b16 {%0,%1}, [%2];"
                 : "=r"(r0), "=r"(r1) : "r"(addr));
}
__device__ __forceinline__ void mma16816(float* c, const uint32_t* a, uint32_t b0, uint32_t b1) {
    asm volatile("mma.sync.aligned.m16n8k16.row.col.f32.f16.f16.f32 "
                 "{%0,%1,%2,%3}, {%4,%5,%6,%7}, {%8,%9}, {%0,%1,%2,%3};"
                 : "+f"(c[0]), "+f"(c[1]), "+f"(c[2]), "+f"(c[3])
                 : "r"(a[0]), "r"(a[1]), "r"(a[2]), "r"(a[3]), "r"(b0), "r"(b1));
}
__device__ __forceinline__ float lrelu(float v) { return (v >= 0.f) ? v : 0.01f * v; }

// ---------- K0: parallel weight prep (1 element per thread) ----------
__global__ void prep_kernel(const float* __restrict__ W1, const float* __restrict__ W2,
                            const float* __restrict__ W3, const float* __restrict__ W4) {
    int idx = blockIdx.x * blockDim.x + threadIdx.x;
    if (idx >= IMG_HALVES) return;
    float v = 0.f;
    if (idx < OFF_W2) {
        int k = idx / WPAD, c = idx % WPAD;
        if (c < 64) v = W1[k * 64 + c];
    } else if (idx < OFF_W3) {
        int j = idx - OFF_W2;
        int k = j / WPAD, c = j % WPAD;
        if (c < 64) v = W2[k * 64 + c];
    } else if (idx < OFF_W4) {
        int j = idx - OFF_W3;
        int k = j / WPAD, c = j % WPAD;
        if (c < 64) v = W3[k * 64 + c];
    } else {
        int j = idx - OFF_W4;
        int k = j >> 3, c = j & 7;
        if (c < 3) v = W4[k * 3 + c];
    }
    unsigned short hv;
    asm("{ .reg .b16 t; cvt.rn.f16.f32 t, %1; mov.b16 %0, t; }" : "=h"(hv) : "f"(v));
    g_prepW[idx] = hv;
}

// ---------- K1: hash encode ----------
__global__ void __launch_bounds__(256)
encode_kernel(const float* __restrict__ X, const float* __restrict__ tab, int n) {
    const int pt = blockIdx.x * 256 + threadIdx.x;
    if (pt >= n) return;
    const float Ntab[16] = N_TAB;
    const float2 xy = __ldg((const float2*)X + pt);
    const float x = xy.x, y = xy.y;

    uint32_t packed[16];
#pragma unroll
    for (int l = 0; l < LVL; l++) {
        float xs = x * Ntab[l], ys = y * Ntab[l];
        float xf = floorf(xs), yf = floorf(ys);
        unsigned xi = (unsigned)xf, yi = (unsigned)yf;
        unsigned hy = (yi * 2654435761u) & TMASK;
        unsigned hx = xi;                 // < 2^18 already
        unsigned hxy = hx ^ hy;
        const float2* tl = (const float2*)tab + (size_t)l * TSZ;
        float2 v0 = __ldg(tl);
        float2 v1 = __ldg(tl + hy);
        float2 v2 = __ldg(tl + hx);
        float2 v3 = __ldg(tl + hxy);
        float fx = xs - xf, fy = ys - yf;
        float cx = 1.f - fx, cy = 1.f - fy;
        float w0 = cx * cy, w1 = cx * fy, w2 = fx * cy, w3 = fx * fy;
        float f0 = w0 * v0.x + w1 * v1.x + w2 * v2.x + w3 * v3.x;
        float f1 = w0 * v0.y + w1 * v1.y + w2 * v2.y + w3 * v3.y;
        packed[l] = pack_h2(f0, f1);
    }
    uint4* dst = g_feat + (size_t)pt * 4;
#pragma unroll
    for (int i = 0; i < 4; i++)
        dst[i] = make_uint4(packed[4 * i], packed[4 * i + 1], packed[4 * i + 2], packed[4 * i + 3]);
}

// ---------- K2: MLP ----------
__global__ void __launch_bounds__(128)
mlp_kernel(const float* __restrict__ b1, const float* __restrict__ b2,
           const float* __restrict__ b3, const float* __restrict__ b4,
           float* __restrict__ out, int n) {
    __shared__ __align__(16) unsigned short sW[IMG_HALVES];      // 24064 B
    __shared__ __align__(16) unsigned short sF[4][32 * FPAD];    // 10240 B
    __shared__ float sb[3][64];
    __shared__ float sb4[8];

    const int tid  = threadIdx.x;
    const int warp = tid >> 5;
    const int lane = tid & 31;

    {
        const uint4* src = (const uint4*)g_prepW;
        uint4* dst = (uint4*)sW;
        for (int i = tid; i < IMG_HALVES / 8; i += 128) dst[i] = src[i];
    }
    if (tid < 64) { sb[0][tid] = b1[tid]; sb[1][tid] = b2[tid]; sb[2][tid] = b3[tid]; }
    if (tid < 8) sb4[tid] = (tid < 3) ? b4[tid] : 0.f;
    __syncthreads();

    const uint32_t uW = smem_u32(sW);
    const uint32_t uF = smem_u32(sF[warp]);
    const int l15 = lane & 15;
    const int lhi = (lane >> 4) << 3;       // +8 halves for upper half-warp
    const int tg2 = (lane & 3) << 1;        // accumulator column pair base
    const int g   = lane >> 2;              // accumulator row base

#pragma unroll 1
    for (int it = 0; it < TILES; it++) {
        const int pbase = (blockIdx.x * TILES + it) * 128 + warp * 32;
        if (pbase >= n) break;

        // stage this warp's 32 feature rows (coalesced uint4 copy into FPAD rows)
        __syncwarp();   // it>0: prior ldsm reads complete before overwrite
        {
            const uint4* src = g_feat + (size_t)pbase * 4;   // 128 uint4
            unsigned short* dstbase = sF[warp];
#pragma unroll
            for (int i = 0; i < 4; i++) {
                int j = lane + 32 * i;                        // 0..127
                uint4 v = src[j];                             // point j>>2, slot j&3
                *(uint4*)(dstbase + (j >> 2) * FPAD + (j & 3) * 8) = v;
            }
        }
        __syncwarp();

        // A fragments: a[mtile][ktile][4]
        uint32_t a[2][4][4];
#pragma unroll
        for (int mt = 0; mt < 2; mt++)
#pragma unroll
            for (int kt = 0; kt < 2; kt++) {
                uint32_t ad = uF + (uint32_t)(((mt * 16 + l15) * FPAD + kt * 16 + lhi) * 2);
                ldsm_x4(a[mt][kt][0], a[mt][kt][1], a[mt][kt][2], a[mt][kt][3], ad);
            }

        const uint32_t woffs[3] = {OFF_W1 * 2u, OFF_W2 * 2u, OFF_W3 * 2u};
        const int nkts[3] = {2, 4, 4};

#pragma unroll 1
        for (int layer = 0; layer < 3; layer++) {
            const uint32_t wb = uW + woffs[layer];
            const int nkt = nkts[layer];
            float c[2][8][4];
#pragma unroll
            for (int mt = 0; mt < 2; mt++)
#pragma unroll
                for (int nt = 0; nt < 8; nt++) {
                    float v0 = sb[layer][8 * nt + tg2];
                    float v1 = sb[layer][8 * nt + tg2 + 1];
                    c[mt][nt][0] = v0; c[mt][nt][1] = v1;
                    c[mt][nt][2] = v0; c[mt][nt][3] = v1;
                }
#pragma unroll
            for (int kt = 0; kt < 4; kt++) {
                if (kt >= nkt) break;
#pragma unroll
                for (int n2 = 0; n2 < 4; n2++) {
                    uint32_t b0, b1, b2, b3;
                    uint32_t bd = wb + (uint32_t)(((kt * 16 + l15) * WPAD + n2 * 16 + lhi) * 2);
                    ldsm_x4_t(b0, b1, b2, b3, bd);
#pragma unroll
                    for (int mt = 0; mt < 2; mt++) {
                        mma16816(c[mt][2 * n2],     a[mt][kt], b0, b1);
                        mma16816(c[mt][2 * n2 + 1], a[mt][kt], b2, b3);
                    }
                }
            }
            // leaky-relu + repack accumulators as next-layer A fragments
#pragma unroll
            for (int mt = 0; mt < 2; mt++)
#pragma unroll
                for (int j = 0; j < 4; j++) {
                    a[mt][j][0] = pack_h2(lrelu(c[mt][2 * j][0]),     lrelu(c[mt][2 * j][1]));
                    a[mt][j][1] = pack_h2(lrelu(c[mt][2 * j][2]),     lrelu(c[mt][2 * j][3]));
                    a[mt][j][2] = pack_h2(lrelu(c[mt][2 * j + 1][0]), lrelu(c[mt][2 * j + 1][1]));
                    a[mt][j][3] = pack_h2(lrelu(c[mt][2 * j + 1][2]), lrelu(c[mt][2 * j + 1][3]));
                }
        }

        // ---- layer 4: 64 -> 3 (single n8 tile, cols 3..7 zero-padded) ----
        float c4[2][4];
#pragma unroll
        for (int mt = 0; mt < 2; mt++) {
            c4[mt][0] = sb4[tg2]; c4[mt][1] = sb4[tg2 + 1];
            c4[mt][2] = sb4[tg2]; c4[mt][3] = sb4[tg2 + 1];
        }
#pragma unroll
        for (int kt = 0; kt < 4; kt++) {
            uint32_t b0, b1;
            uint32_t bd = uW + OFF_W4 * 2u + (uint32_t)(((kt * 16 + l15) * 8) * 2);
            ldsm_x2_t(b0, b1, bd);
#pragma unroll
            for (int mt = 0; mt < 2; mt++) mma16816(c4[mt], a[mt][kt], b0, b1);
        }

        // relu + predicated stores: rows (g, g+8) per m-tile, cols (tg2, tg2+1)
#pragma unroll
        for (int mt = 0; mt < 2; mt++) {
            int p0 = pbase + mt * 16 + g;
            int p1 = p0 + 8;
            float v0 = fmaxf(c4[mt][0], 0.f), v1 = fmaxf(c4[mt][1], 0.f);
            float v2 = fmaxf(c4[mt][2], 0.f), v3 = fmaxf(c4[mt][3], 0.f);
            if (tg2 < 3) {
                if (p0 < n) out[3 * p0 + tg2] = v0;
                if (p1 < n) out[3 * p1 + tg2] = v2;
            }
            if (tg2 + 1 < 3) {
                if (p0 < n) out[3 * p0 + tg2 + 1] = v1;
                if (p1 < n) out[3 * p1 + tg2 + 1] = v3;
            }
        }
    }
}

extern "C" void kernel_launch(void* const* d_in, const int* in_sizes, int n_in,
                              void* d_out, int out_size) {
    const float* X   = (const float*)d_in[0];
    const float* tab = (const float*)d_in[1];
    const float* W1  = (const float*)d_in[2];
    const float* b1  = (const float*)d_in[3];
    const float* W2  = (const float*)d_in[4];
    const float* b2  = (const float*)d_in[5];
    const float* W3  = (const float*)d_in[6];
    const float* b3  = (const float*)d_in[7];
    const float* W4  = (const float*)d_in[8];
    const float* b4  = (const float*)d_in[9];
    float* out = (float*)d_out;

    int n = in_sizes[0] / 2;
    prep_kernel<<<(IMG_HALVES + 255) / 256, 256>>>(W1, W2, W3, W4);
    encode_kernel<<<(n + 255) / 256, 256>>>(X, tab, n);
    int ptile = 128 * TILES;
    mlp_kernel<<<(n + ptile - 1) / ptile, 128>>>(b1, b2, b3, b4, out, n);
}